// round 5
// baseline (speedup 1.0000x reference)
#include <cuda_runtime.h>
#include <cstdint>

#define NB   2048
#define INS  512
#define SEQL 128
#define NH   12
#define NOUT 3
#define BPB  4   // batches per block in pre_kernel (1 warp per batch)

// scratch (allocation-free contract: __device__ globals)
__device__ float g_pre[(size_t)SEQL * NB * NH];   // [s][b][h]  ~12.6 MB
__device__ float g_hbwd[NB * NH];

__device__ __forceinline__ unsigned long long fma2(unsigned long long a,
                                                   unsigned long long b,
                                                   unsigned long long c) {
    unsigned long long d;
    asm("fma.rn.f32x2 %0, %1, %2, %3;" : "=l"(d) : "l"(a), "l"(b), "l"(c));
    return d;
}
__device__ __forceinline__ unsigned long long pk2(float f) {
    unsigned long long u;
    asm("mov.b64 %0, {%1, %1};" : "=l"(u) : "f"(f));
    return u;
}
__device__ __forceinline__ float ftanh(float x) {
    float e = __expf(2.0f * x);
    return 1.0f - __fdividef(2.0f, e + 1.0f);
}

// ---------------------------------------------------------------------------
// Kernel 1: pre[s,b,h] = sum_i emb[x[b,i], s] * w_ih_f[h,i]
// grid (NB/BPB, 2); warp per batch; lane owns s0 = 64*y + 2*lane, s1 = s0+1.
// __launch_bounds__(128, 6): cap regs at 85 -> 6 blocks/SM = 24 warps/SM so
// the FFMA2 rt=2 pipe (45us floor at 100%) stays fed. 8-deep ping-pong e
// prefetch; weights as float2 pairs in smem (3 broadcast LDS.128 per i).
// ---------------------------------------------------------------------------
extern "C" __global__ void __launch_bounds__(128, 6)
pre_kernel(const int* __restrict__ x, const float* __restrict__ emb,
           const float* __restrict__ wih) {
    __shared__ float2 w2[INS * 6];   // 24 KB: w2[i*6+k] = (w[2k,i], w[2k+1,i])
    __shared__ int    xs[BPB * INS]; // 8 KB

    const int tid = threadIdx.x;
    const int b0 = blockIdx.x * BPB;

    for (int t = tid; t < INS * 6; t += 128) {
        int i = t & (INS - 1);
        int k = t >> 9;              // 0..5
        w2[i * 6 + k] = make_float2(wih[(2 * k) * INS + i],
                                    wih[(2 * k + 1) * INS + i]);
    }
    for (int t = tid; t < BPB * INS; t += 128)
        xs[t] = x[(size_t)b0 * INS + t];
    __syncthreads();

    const int warp = tid >> 5;
    const int lane = tid & 31;
    const int b = b0 + warp;
    const int sbase = blockIdx.y * 64 + lane * 2;
    const int* xrow = xs + warp * INS;
    const float* ebase = emb + sbase;

    unsigned long long a0[6], a1[6];   // s0 / s1 accumulators, h-pairs
#pragma unroll
    for (int k = 0; k < 6; k++) { a0[k] = 0ull; a1[k] = 0ull; }

    float2 eA[8], eB[8];

#define LOADE(buf, base_i)                                                    \
    do {                                                                      \
        int4 qa = *(const int4*)(xrow + (base_i));                            \
        int4 qb = *(const int4*)(xrow + (base_i) + 4);                        \
        buf[0] = *(const float2*)(ebase + (size_t)qa.x * SEQL);              \
        buf[1] = *(const float2*)(ebase + (size_t)qa.y * SEQL);              \
        buf[2] = *(const float2*)(ebase + (size_t)qa.z * SEQL);              \
        buf[3] = *(const float2*)(ebase + (size_t)qa.w * SEQL);              \
        buf[4] = *(const float2*)(ebase + (size_t)qb.x * SEQL);              \
        buf[5] = *(const float2*)(ebase + (size_t)qb.y * SEQL);              \
        buf[6] = *(const float2*)(ebase + (size_t)qb.z * SEQL);              \
        buf[7] = *(const float2*)(ebase + (size_t)qb.w * SEQL);              \
    } while (0)

#define COMPUTE8(buf, base_i)                                                 \
    do {                                                                      \
        _Pragma("unroll")                                                     \
        for (int u = 0; u < 8; u++) {                                         \
            unsigned long long p0 = pk2(buf[u].x);                            \
            unsigned long long p1 = pk2(buf[u].y);                            \
            const ulonglong2* wv =                                            \
                (const ulonglong2*)(w2 + (size_t)((base_i) + u) * 6);         \
            ulonglong2 wA = wv[0], wB = wv[1], wC = wv[2];                    \
            a0[0] = fma2(p0, wA.x, a0[0]);                                    \
            a1[0] = fma2(p1, wA.x, a1[0]);                                    \
            a0[1] = fma2(p0, wA.y, a0[1]);                                    \
            a1[1] = fma2(p1, wA.y, a1[1]);                                    \
            a0[2] = fma2(p0, wB.x, a0[2]);                                    \
            a1[2] = fma2(p1, wB.x, a1[2]);                                    \
            a0[3] = fma2(p0, wB.y, a0[3]);                                    \
            a1[3] = fma2(p1, wB.y, a1[3]);                                    \
            a0[4] = fma2(p0, wC.x, a0[4]);                                    \
            a1[4] = fma2(p1, wC.x, a1[4]);                                    \
            a0[5] = fma2(p0, wC.y, a0[5]);                                    \
            a1[5] = fma2(p1, wC.y, a1[5]);                                    \
        }                                                                     \
    } while (0)

    LOADE(eA, 0);

#pragma unroll 1
    for (int i0 = 0; i0 < INS; i0 += 16) {
        LOADE(eB, i0 + 8);                           // second half in flight
        COMPUTE8(eA, i0);                            // compute first half
        LOADE(eA, (i0 + 16 < INS) ? (i0 + 16) : 0);  // next chunk (tail clamp)
        COMPUTE8(eB, i0 + 8);                        // compute second half
    }
#undef LOADE
#undef COMPUTE8

    {
        ulonglong2* d = (ulonglong2*)(g_pre + ((size_t)sbase * NB + b) * NH);
        ulonglong2 v0, v1, v2;
        v0.x = a0[0]; v0.y = a0[1];
        v1.x = a0[2]; v1.y = a0[3];
        v2.x = a0[4]; v2.y = a0[5];
        d[0] = v0; d[1] = v1; d[2] = v2;
    }
    {
        ulonglong2* d =
            (ulonglong2*)(g_pre + ((size_t)(sbase + 1) * NB + b) * NH);
        ulonglong2 v0, v1, v2;
        v0.x = a1[0]; v0.y = a1[1];
        v1.x = a1[2]; v1.y = a1[3];
        v2.x = a1[4]; v2.y = a1[5];
        d[0] = v0; d[1] = v1; d[2] = v2;
    }
}

// ---------------------------------------------------------------------------
// Kernel 2: h_bwd — warp per batch, MLP=16 prefetch.
// ---------------------------------------------------------------------------
extern "C" __global__ void __launch_bounds__(256)
bwd_kernel(const int* __restrict__ x, const float* __restrict__ emb,
           const float* __restrict__ wir, const float* __restrict__ bir,
           const float* __restrict__ bhr) {
    __shared__ float ws[NH * INS];   // 24 KB
    const int tid = threadIdx.x;
    for (int t = tid; t < NH * INS; t += 256) ws[t] = wir[t];
    __syncthreads();

    const int warp = tid >> 5, lane = tid & 31;
    const int b = blockIdx.x * 8 + warp;

    int idxv[16];
#pragma unroll
    for (int j = 0; j < 16; j++)
        idxv[j] = x[(size_t)b * INS + lane + 32 * j];
    float ev[16];
#pragma unroll
    for (int j = 0; j < 16; j++)
        ev[j] = emb[(size_t)idxv[j] * SEQL + (SEQL - 1)];

    float p[NH];
#pragma unroll
    for (int h = 0; h < NH; h++) p[h] = 0.f;
#pragma unroll
    for (int j = 0; j < 16; j++) {
        const int i = lane + 32 * j;
#pragma unroll
        for (int h = 0; h < NH; h++) p[h] = fmaf(ev[j], ws[h * INS + i], p[h]);
    }
#pragma unroll
    for (int h = 0; h < NH; h++) {
        float v = p[h];
#pragma unroll
        for (int o = 16; o; o >>= 1) v += __shfl_xor_sync(0xffffffffu, v, o);
        p[h] = v;
    }
    if (lane == 0) {
        float r[NH];
#pragma unroll
        for (int h = 0; h < NH; h++) r[h] = ftanh(p[h] + bir[h] + bhr[h]);
        float4* d = (float4*)(g_hbwd + (size_t)b * NH);
        d[0] = make_float4(r[0], r[1], r[2], r[3]);
        d[1] = make_float4(r[4], r[5], r[6], r[7]);
        d[2] = make_float4(r[8], r[9], r[10], r[11]);
    }
}

// ---------------------------------------------------------------------------
// Kernel 3: forward scan + fused FC epilogue.
// 2 independent batch-chains per thread (ILP on the latency-bound recurrence)
// and prefetch distance 3 so the ~250cyc L2 load of pre[s+3] is fully hidden
// behind 3 recurrence steps (~300cyc). 16 lanes per chain, shfl width 16.
// ---------------------------------------------------------------------------
extern "C" __global__ void __launch_bounds__(256)
scan_kernel(const float* __restrict__ whh, const float* __restrict__ bih,
            const float* __restrict__ bhh, const float* __restrict__ fcw,
            const float* __restrict__ fcb, float* __restrict__ out) {
    const int tid = threadIdx.x;
    const int slot = tid >> 4;            // 0..15
    const int hl = tid & 15;
    const int hc = hl < NH ? hl : 0;
    const int bA = blockIdx.x * 32 + slot;
    const int bB = bA + 16;

    float wrow[NH];
#pragma unroll
    for (int j = 0; j < NH; j++) wrow[j] = whh[hc * NH + j];
    const float bias = bih[hc] + bhh[hc];

    const float* psA = g_pre + (size_t)bA * NH + hc;
    const float* psB = g_pre + (size_t)bB * NH + hc;
    const size_t sstr = (size_t)NB * NH;

    float hA = 0.f, hB = 0.f;
    // rolling prefetch window of 3
    float pA0 = psA[0], pA1 = psA[sstr], pA2 = psA[2 * sstr];
    float pB0 = psB[0], pB1 = psB[sstr], pB2 = psB[2 * sstr];

    for (int s = 0; s < SEQL; s++) {
        float pA = pA0, pB = pB0;
        pA0 = pA1; pA1 = pA2;
        pB0 = pB1; pB1 = pB2;
        int sl = (s + 3 < SEQL) ? (s + 3) : 0;
        pA2 = psA[(size_t)sl * sstr];
        pB2 = psB[(size_t)sl * sstr];

        float vA[NH], vB[NH];
#pragma unroll
        for (int j = 0; j < NH; j++) {
            vA[j] = __shfl_sync(0xffffffffu, hA, j, 16);
            vB[j] = __shfl_sync(0xffffffffu, hB, j, 16);
        }
        float tA0 = fmaf(vA[0], wrow[0], pA + bias);
        float tB0 = fmaf(vB[0], wrow[0], pB + bias);
        float tA1 = vA[1] * wrow[1], tB1 = vB[1] * wrow[1];
        float tA2 = vA[2] * wrow[2], tB2 = vB[2] * wrow[2];
#pragma unroll
        for (int j = 3; j < NH; j += 3) {
            tA0 = fmaf(vA[j    ], wrow[j    ], tA0);
            tB0 = fmaf(vB[j    ], wrow[j    ], tB0);
            tA1 = fmaf(vA[j + 1], wrow[j + 1], tA1);
            tB1 = fmaf(vB[j + 1], wrow[j + 1], tB1);
            tA2 = fmaf(vA[j + 2], wrow[j + 2], tA2);
            tB2 = fmaf(vB[j + 2], wrow[j + 2], tB2);
        }
        hA = ftanh(tA0 + tA1 + tA2);
        hB = ftanh(tB0 + tB1 + tB2);
    }

    float vA[NH], vB[NH];
#pragma unroll
    for (int j = 0; j < NH; j++) {
        vA[j] = __shfl_sync(0xffffffffu, hA, j, 16);
        vB[j] = __shfl_sync(0xffffffffu, hB, j, 16);
    }
    if (hl < NOUT) {
        float oA = fcb[hl], oB = fcb[hl];
        const float* hbA = g_hbwd + (size_t)bA * NH;
        const float* hbB = g_hbwd + (size_t)bB * NH;
#pragma unroll
        for (int j = 0; j < NH; j++) {
            oA = fmaf(vA[j], fcw[hl * 2 * NH + j], oA);
            oB = fmaf(vB[j], fcw[hl * 2 * NH + j], oB);
        }
#pragma unroll
        for (int j = 0; j < NH; j++) {
            oA = fmaf(hbA[j], fcw[hl * 2 * NH + NH + j], oA);
            oB = fmaf(hbB[j], fcw[hl * 2 * NH + NH + j], oB);
        }
        out[bA * NOUT + hl] = oA;
        out[bB * NOUT + hl] = oB;
    }
}

// ---------------------------------------------------------------------------
extern "C" void kernel_launch(void* const* d_in, const int* in_sizes, int n_in,
                              void* d_out, int out_size) {
    const int*   x      = (const int*)  d_in[0];
    const float* emb    = (const float*)d_in[1];
    const float* w_ih_f = (const float*)d_in[2];
    const float* w_hh_f = (const float*)d_in[3];
    const float* b_ih_f = (const float*)d_in[4];
    const float* b_hh_f = (const float*)d_in[5];
    const float* w_ih_r = (const float*)d_in[6];
    // d_in[7] = w_hh_r (unused: reference consumes only the one-step reverse state)
    const float* b_ih_r = (const float*)d_in[8];
    const float* b_hh_r = (const float*)d_in[9];
    const float* fc_w   = (const float*)d_in[10];
    const float* fc_b   = (const float*)d_in[11];
    float* out = (float*)d_out;

    pre_kernel<<<dim3(NB / BPB, 2), 128>>>(x, emb, w_ih_f);
    bwd_kernel<<<NB / 8, 256>>>(x, emb, w_ih_r, b_ih_r, b_hh_r);
    scan_kernel<<<NB / 32, 256>>>(w_hh_f, b_ih_f, b_hh_f, fc_w, fc_b, out);
}